// round 16
// baseline (speedup 1.0000x reference)
#include <cuda_runtime.h>
#include <cuda_fp16.h>
#include <math.h>

// Problem caps (from reference): N=50000 nodes, E=800000 edges, D=64.
#define MAXN 50000
#define MAXE 800000
#define MAXEP (MAXE + 8 * MAXN)   // padded CSR capacity (pad-to-8 per node)
#define SCAN_B 256

// Scratch (device globals — no allocation allowed in kernel_launch).
__device__ __align__(16) __half2 g_tmph[(MAXN + 1) * 32]; // messages fp16; row n = zeros
__device__ __align__(16) __half2 g_hh[MAXN * 32];    // layer activations, fp16 (GEMM input)
__device__ float g_dinv[MAXN];        // 1/sqrt(deg+1)
__device__ int   g_deg[MAXN];
__device__ int   g_cursor[MAXN];      // preloaded with rowptr by k_scan
__device__ int   g_rowptr[MAXN];      // padded row start (32B aligned)
__device__ __align__(16) int g_col[MAXEP];  // padded CSR: src indices; pad slots = n
__device__ __align__(16) int g_dummy[8];    // sentinel group (all = n)
__device__ int   g_total;             // ticket counter for tile bases (padded units)

// ---------------------------------------------------------------------------
// Setup stage 1 (fat kernel), three independent block ranges:
//   [0, nbe)            : count degrees (atomics)
//   [nbe, nbe+nbc)      : cast x fp32 -> g_hh fp16
//   [nbe+nbc, ...)      : prefill g_col + g_dummy with n; zero dummy msg row
// ---------------------------------------------------------------------------
__global__ void k_setup1(const int* __restrict__ dst, int e,
                         const float* __restrict__ x, int n16,
                         int nbe, int nbc, int n) {
    int b = blockIdx.x;
    if (b < nbe) {
        int i = b * blockDim.x + threadIdx.x;
        if (i == 0) g_total = 0;
        if (i < e) atomicAdd(&g_deg[dst[i]], 1);
    } else if (b < nbe + nbc) {
        int i = (b - nbe) * blockDim.x + threadIdx.x;
        if (i < n16) {
            float4 v = ((const float4*)x)[i];
            __half2 h0 = __floats2half2_rn(v.x, v.y);
            __half2 h1 = __floats2half2_rn(v.z, v.w);
            uint2 st; st.x = *(unsigned*)&h0; st.y = *(unsigned*)&h1;
            ((uint2*)g_hh)[i] = st;
        }
    } else {
        int bb = b - nbe - nbc;
        int i = bb * blockDim.x + threadIdx.x;   // int4 index
        if (i < MAXEP / 4) {
            ((int4*)g_col)[i] = make_int4(n, n, n, n);
        }
        if (bb == 0) {
            if (threadIdx.x < 32)                // zero dummy message row n
                g_tmph[n * 32 + threadIdx.x] = __floats2half2_rn(0.f, 0.f);
            if (threadIdx.x >= 32 && threadIdx.x < 40)
                g_dummy[threadIdx.x - 32] = n;
        }
    }
}

// Single-pass scan over PADDED degrees ((deg+7)&~7); per-tile exclusive scan,
// tile base via atomicAdd ticket (order-free — agg derives its own end).
__global__ void k_scan(int n) {
    int i = blockIdx.x * SCAN_B + threadIdx.x;
    int lane = threadIdx.x & 31, wid = threadIdx.x >> 5;
    int v = (i < n) ? g_deg[i] : 0;
    int pad = (v + 7) & ~7;
    float di = rsqrtf((float)(v + 1));   // +1 self-loop

    int x = pad;
#pragma unroll
    for (int o = 1; o < 32; o <<= 1) {
        int t = __shfl_up_sync(0xffffffffu, x, o);
        if (lane >= o) x += t;
    }
    __shared__ int wsum[8];
    __shared__ int base;
    if (lane == 31) wsum[wid] = x;
    __syncthreads();
    if (wid == 0) {
        int s = (lane < 8) ? wsum[lane] : 0;
#pragma unroll
        for (int o = 1; o < 8; o <<= 1) {
            int t = __shfl_up_sync(0xffffffffu, s, o);
            if (lane >= o) s += t;
        }
        if (lane < 8) wsum[lane] = s;
    }
    __syncthreads();
    if (threadIdx.x == 0) base = atomicAdd(&g_total, wsum[7]);
    __syncthreads();
    int excl = base + x - pad + (wid ? wsum[wid - 1] : 0);
    if (i < n) {
        g_rowptr[i] = excl;
        g_cursor[i] = excl;
        g_dinv[i]   = di;
    }
}

// ---------------------------------------------------------------------------
// GEMM device body (HMMA m16n8k16): tmp'[r,:] = dinv[r]*(g_hh[r,:] @ W), fp16.
// Tile 128x64, 8 warps, K=64. fp16 in, fp32 accum. Conflict-free smem strides.
// ---------------------------------------------------------------------------
#define AS_STRIDE 36
#define WP_STRIDE 68

__device__ __forceinline__ void gemm_body(const float* __restrict__ W, int n,
                                          int gemm_block, int tid,
                                          unsigned* As, unsigned* Wp) {
    int block_row = gemm_block * 128;

#pragma unroll
    for (int j = 0; j < 8; ++j) {
        int idx = tid + 256 * j;            // 2048 entries
        int kk = idx >> 6, c = idx & 63;
        __half2 p = __floats2half2_rn(W[(2 * kk) * 64 + c], W[(2 * kk + 1) * 64 + c]);
        Wp[kk * WP_STRIDE + c] = *(unsigned*)&p;
    }
#pragma unroll
    for (int j = 0; j < 8; ++j) {
        int idx = tid + 256 * j;
        int r = idx >> 4, c4 = idx & 15;
        int gr = block_row + r;
        uint2 v = make_uint2(0u, 0u);
        if (gr < n) v = ((const uint2*)g_hh)[gr * 16 + c4];
        *(uint2*)&As[r * AS_STRIDE + c4 * 2] = v;
    }
    __syncthreads();

    int w = tid >> 5, l = tid & 31;
    int t = l & 3, g = l >> 2;
    int r0 = w * 16 + g;                 // rows r0, r0+8

    float acc[8][4];
#pragma unroll
    for (int nt = 0; nt < 8; ++nt)
#pragma unroll
        for (int c = 0; c < 4; ++c) acc[nt][c] = 0.f;

#pragma unroll
    for (int ks = 0; ks < 4; ++ks) {
        unsigned a0 = As[r0 * AS_STRIDE + 8 * ks + t];
        unsigned a1 = As[(r0 + 8) * AS_STRIDE + 8 * ks + t];
        unsigned a2 = As[r0 * AS_STRIDE + 8 * ks + t + 4];
        unsigned a3 = As[(r0 + 8) * AS_STRIDE + 8 * ks + t + 4];
#pragma unroll
        for (int nt = 0; nt < 8; ++nt) {
            unsigned b0 = Wp[(8 * ks + t) * WP_STRIDE + 8 * nt + g];
            unsigned b1 = Wp[(8 * ks + t + 4) * WP_STRIDE + 8 * nt + g];
            asm("mma.sync.aligned.m16n8k16.row.col.f32.f16.f16.f32 "
                "{%0,%1,%2,%3},{%4,%5,%6,%7},{%8,%9},{%0,%1,%2,%3};"
                : "+f"(acc[nt][0]), "+f"(acc[nt][1]), "+f"(acc[nt][2]), "+f"(acc[nt][3])
                : "r"(a0), "r"(a1), "r"(a2), "r"(a3), "r"(b0), "r"(b1));
        }
    }

    int gr0 = block_row + r0;
    int gr1 = gr0 + 8;
    float ds0 = (gr0 < n) ? g_dinv[gr0] : 0.f;
    float ds1 = (gr1 < n) ? g_dinv[gr1] : 0.f;
#pragma unroll
    for (int nt = 0; nt < 8; ++nt) {
        if (gr0 < n) {
            __half2 h = __floats2half2_rn(ds0 * acc[nt][0], ds0 * acc[nt][1]);
            g_tmph[gr0 * 32 + 4 * nt + t] = h;
        }
        if (gr1 < n) {
            __half2 h = __floats2half2_rn(ds1 * acc[nt][2], ds1 * acc[nt][3]);
            g_tmph[gr1 * 32 + 4 * nt + t] = h;
        }
    }
}

// Plain GEMM launch (layers 2,3).
__global__ void k_gemm(const float* __restrict__ W, int n) {
    __shared__ unsigned As[128 * AS_STRIDE];
    __shared__ unsigned Wp[32 * WP_STRIDE];
    gemm_body(W, n, blockIdx.x, threadIdx.x, As, Wp);
}

// Fat kernel: blocks [0,nbe) scatter edges into padded CSR (fill); the rest
// run GEMM layer 1. Independent work.
__global__ void k_fill_gemm(const int* __restrict__ src, const int* __restrict__ dst,
                            int e, const float* __restrict__ W, int n, int nbe) {
    __shared__ unsigned As[128 * AS_STRIDE];
    __shared__ unsigned Wp[32 * WP_STRIDE];
    int b = blockIdx.x;
    if (b < nbe) {
        int i = b * blockDim.x + threadIdx.x;
        if (i < e) {
            int pos = atomicAdd(&g_cursor[dst[i]], 1);
            g_col[pos] = src[i];
        }
    } else {
        gemm_body(W, n, b - nbe, threadIdx.x, As, Wp);
    }
}

// ---------------------------------------------------------------------------
// Aggregation + bias + ELU. TWO nodes per warp, interleaved 8-slot groups:
// 16 outstanding gathers across the two nodes' chains hides the idx->gather
// L2 latency. Finished node redirects its idx pointer to g_dummy (-> zero
// row, exact). fp16 HADD2 trees, fp32 accumulate.
// out = ELU( dinv[i]*(sum_s tmp'[s] + tmp'[i]) + b )
// ---------------------------------------------------------------------------
__device__ __forceinline__ void agg_group8(const int4 i0, const int4 i1, int lane,
                                           float& ax, float& ay) {
    __half2 v0 = g_tmph[i0.x * 32 + lane];
    __half2 v1 = g_tmph[i0.y * 32 + lane];
    __half2 v2 = g_tmph[i0.z * 32 + lane];
    __half2 v3 = g_tmph[i0.w * 32 + lane];
    __half2 v4 = g_tmph[i1.x * 32 + lane];
    __half2 v5 = g_tmph[i1.y * 32 + lane];
    __half2 v6 = g_tmph[i1.z * 32 + lane];
    __half2 v7 = g_tmph[i1.w * 32 + lane];
    __half2 q0 = __hadd2(__hadd2(v0, v1), __hadd2(v2, v3));
    __half2 q1 = __hadd2(__hadd2(v4, v5), __hadd2(v6, v7));
    float2 f0 = __half22float2(q0);
    float2 f1 = __half22float2(q1);
    ax += f0.x + f1.x;
    ay += f0.y + f1.y;
}

__device__ __forceinline__ void agg_epilogue(int w, int lane, float ax, float ay,
                                             const float* bias, float* out,
                                             int col_off, int last) {
    float di = g_dinv[w];
    float2 vs = __half22float2(g_tmph[w * 32 + lane]);
    float2 bb = ((const float2*)bias)[lane];
    ax = fmaf(di, ax + vs.x, bb.x);
    ay = fmaf(di, ay + vs.y, bb.y);
    ax = ax > 0.f ? ax : expm1f(ax);
    ay = ay > 0.f ? ay : expm1f(ay);
    if (!last) g_hh[w * 32 + lane] = __floats2half2_rn(ax, ay);
    float* orow = out + (size_t)w * 192 + col_off;
    ((float2*)orow)[lane] = make_float2(ax, ay);
}

__global__ void k_agg(const float* __restrict__ bias,
                      float* __restrict__ out, int col_off, int n, int last) {
    int pair = (blockIdx.x * blockDim.x + threadIdx.x) >> 5;
    int lane = threadIdx.x & 31;
    int w0 = pair * 2;
    int w1 = w0 + 1;
    if (w0 >= n) return;
    bool has1 = (w1 < n);

    int beg0 = g_rowptr[w0];
    int pad0 = (g_deg[w0] + 7) & ~7;
    int beg1 = has1 ? g_rowptr[w1] : 0;
    int pad1 = has1 ? ((g_deg[w1] + 7) & ~7) : 0;
    int gmax = (pad0 > pad1 ? pad0 : pad1) >> 3;

    float ax0 = 0.f, ay0 = 0.f, ax1 = 0.f, ay1 = 0.f;
    for (int g = 0; g < gmax; ++g) {
        int off = g << 3;
        const int* p0 = (off < pad0) ? &g_col[beg0 + off] : g_dummy;
        const int* p1 = (off < pad1) ? &g_col[beg1 + off] : g_dummy;
        int4 a0 = *(const int4*)p0;
        int4 a1 = *(const int4*)(p0 + 4);
        int4 b0 = *(const int4*)p1;
        int4 b1 = *(const int4*)(p1 + 4);
        agg_group8(a0, a1, lane, ax0, ay0);
        agg_group8(b0, b1, lane, ax1, ay1);
    }
    agg_epilogue(w0, lane, ax0, ay0, bias, out, col_off, last);
    if (has1) agg_epilogue(w1, lane, ax1, ay1, bias, out, col_off, last);
}

// ---------------------------------------------------------------------------
extern "C" void kernel_launch(void* const* d_in, const int* in_sizes, int n_in,
                              void* d_out, int out_size) {
    const float* x  = (const float*)d_in[0];
    const int*   ei = (const int*)d_in[1];
    const float* W[3] = { (const float*)d_in[2], (const float*)d_in[4], (const float*)d_in[6] };
    const float* B[3] = { (const float*)d_in[3], (const float*)d_in[5], (const float*)d_in[7] };
    int n = in_sizes[0] / 64;
    int e = in_sizes[1] / 2;
    const int* src = ei;
    const int* dst = ei + e;
    float* out = (float*)d_out;

    int nb_e = (e + 255) / 256;
    int nscan = (n + SCAN_B - 1) / SCAN_B;
    int n16 = n * 16;                        // float4 count of x
    int nb_c = (n16 + 255) / 256;            // cast blocks
    int nb_p = (MAXEP / 4 + 255) / 256;      // prefill blocks (int4)
    int gemm_blocks = (n + 127) / 128;
    int agg_blocks = (n + 15) / 16;          // 8 warps x 2 nodes per 256-thread block

    void* degptr = nullptr;
    cudaGetSymbolAddress(&degptr, g_deg);
    cudaMemsetAsync(degptr, 0, (size_t)n * sizeof(int));

    k_setup1<<<nb_e + nb_c + nb_p, 256>>>(dst, e, x, n16, nb_e, nb_c, n);
    k_scan<<<nscan, SCAN_B>>>(n);
    k_fill_gemm<<<nb_e + gemm_blocks, 256>>>(src, dst, e, W[0], n, nb_e);
    k_agg<<<agg_blocks, 256>>>(B[0], out, 0, n, 0);
    for (int l = 1; l < 3; ++l) {
        k_gemm<<<gemm_blocks, 256>>>(W[l], n);
        k_agg<<<agg_blocks, 256>>>(B[l], out, l * 64, n, l == 2 ? 1 : 0);
    }
}

// round 17
// speedup vs baseline: 1.0560x; 1.0560x over previous
#include <cuda_runtime.h>
#include <cuda_fp16.h>
#include <math.h>

// Problem caps (from reference): N=50000 nodes, E=800000 edges, D=64.
#define MAXN 50000
#define MAXE 800000
#define MAXEP (MAXE + 8 * MAXN)   // padded CSR capacity (pad-to-8 per node)
#define SCAN_B 256

// Scratch (device globals — no allocation allowed in kernel_launch).
__device__ __align__(16) __half2 g_tmph[(MAXN + 1) * 32]; // messages fp16; row n = zeros
__device__ __align__(16) __half2 g_hh[MAXN * 32];    // layer activations, fp16 (GEMM input)
__device__ float g_dinv[MAXN];        // 1/sqrt(deg+1)
__device__ int   g_deg[MAXN];
__device__ int   g_cursor[MAXN];      // preloaded with rowptr by k_scan
__device__ __align__(8) int2 g_meta[MAXN];  // (padded row start, deg)
__device__ __align__(16) int g_col[MAXEP];  // padded CSR: src indices; pad slots = n
__device__ int   g_total;             // ticket counter for tile bases (padded units)

// ---------------------------------------------------------------------------
// Setup stage 1 (fat kernel), three independent block ranges:
//   [0, nbe)            : count degrees (atomics)
//   [nbe, nbe+nbc)      : cast x fp32 -> g_hh fp16
//   [nbe+nbc, ...)      : prefill g_col with n (pad sentinel); zero dummy row
// ---------------------------------------------------------------------------
__global__ void k_setup1(const int* __restrict__ dst, int e,
                         const float* __restrict__ x, int n16,
                         int nbe, int nbc, int n) {
    int b = blockIdx.x;
    if (b < nbe) {
        int i = b * blockDim.x + threadIdx.x;
        if (i == 0) g_total = 0;
        if (i < e) atomicAdd(&g_deg[dst[i]], 1);
    } else if (b < nbe + nbc) {
        int i = (b - nbe) * blockDim.x + threadIdx.x;
        if (i < n16) {
            float4 v = ((const float4*)x)[i];
            __half2 h0 = __floats2half2_rn(v.x, v.y);
            __half2 h1 = __floats2half2_rn(v.z, v.w);
            uint2 st; st.x = *(unsigned*)&h0; st.y = *(unsigned*)&h1;
            ((uint2*)g_hh)[i] = st;
        }
    } else {
        int bb = b - nbe - nbc;
        int i = bb * blockDim.x + threadIdx.x;   // int4 index
        if (i < MAXEP / 4) {
            ((int4*)g_col)[i] = make_int4(n, n, n, n);
        }
        if (bb == 0 && threadIdx.x < 32) {       // zero dummy message row n
            g_tmph[n * 32 + threadIdx.x] = __floats2half2_rn(0.f, 0.f);
        }
    }
}

// Single-pass scan over PADDED degrees ((deg+7)&~7); per-tile exclusive scan,
// tile base via atomicAdd ticket (order-free — agg derives its own end).
// Writes packed (rowptr, deg) metadata for agg's single-load prologue.
__global__ void k_scan(int n) {
    int i = blockIdx.x * SCAN_B + threadIdx.x;
    int lane = threadIdx.x & 31, wid = threadIdx.x >> 5;
    int v = (i < n) ? g_deg[i] : 0;
    int pad = (v + 7) & ~7;
    float di = rsqrtf((float)(v + 1));   // +1 self-loop

    int x = pad;
#pragma unroll
    for (int o = 1; o < 32; o <<= 1) {
        int t = __shfl_up_sync(0xffffffffu, x, o);
        if (lane >= o) x += t;
    }
    __shared__ int wsum[8];
    __shared__ int base;
    if (lane == 31) wsum[wid] = x;
    __syncthreads();
    if (wid == 0) {
        int s = (lane < 8) ? wsum[lane] : 0;
#pragma unroll
        for (int o = 1; o < 8; o <<= 1) {
            int t = __shfl_up_sync(0xffffffffu, s, o);
            if (lane >= o) s += t;
        }
        if (lane < 8) wsum[lane] = s;
    }
    __syncthreads();
    if (threadIdx.x == 0) base = atomicAdd(&g_total, wsum[7]);
    __syncthreads();
    int excl = base + x - pad + (wid ? wsum[wid - 1] : 0);
    if (i < n) {
        g_meta[i]   = make_int2(excl, v);
        g_cursor[i] = excl;
        g_dinv[i]   = di;
    }
}

// ---------------------------------------------------------------------------
// GEMM device body (HMMA m16n8k16): tmp'[r,:] = dinv[r]*(g_hh[r,:] @ W), fp16.
// Tile 128x64, 8 warps, K=64. fp16 in, fp32 accum. Conflict-free smem strides.
// ---------------------------------------------------------------------------
#define AS_STRIDE 36
#define WP_STRIDE 68

__device__ __forceinline__ void gemm_body(const float* __restrict__ W, int n,
                                          int gemm_block, int tid,
                                          unsigned* As, unsigned* Wp) {
    int block_row = gemm_block * 128;

#pragma unroll
    for (int j = 0; j < 8; ++j) {
        int idx = tid + 256 * j;            // 2048 entries
        int kk = idx >> 6, c = idx & 63;
        __half2 p = __floats2half2_rn(W[(2 * kk) * 64 + c], W[(2 * kk + 1) * 64 + c]);
        Wp[kk * WP_STRIDE + c] = *(unsigned*)&p;
    }
#pragma unroll
    for (int j = 0; j < 8; ++j) {
        int idx = tid + 256 * j;
        int r = idx >> 4, c4 = idx & 15;
        int gr = block_row + r;
        uint2 v = make_uint2(0u, 0u);
        if (gr < n) v = ((const uint2*)g_hh)[gr * 16 + c4];
        *(uint2*)&As[r * AS_STRIDE + c4 * 2] = v;
    }
    __syncthreads();

    int w = tid >> 5, l = tid & 31;
    int t = l & 3, g = l >> 2;
    int r0 = w * 16 + g;                 // rows r0, r0+8

    float acc[8][4];
#pragma unroll
    for (int nt = 0; nt < 8; ++nt)
#pragma unroll
        for (int c = 0; c < 4; ++c) acc[nt][c] = 0.f;

#pragma unroll
    for (int ks = 0; ks < 4; ++ks) {
        unsigned a0 = As[r0 * AS_STRIDE + 8 * ks + t];
        unsigned a1 = As[(r0 + 8) * AS_STRIDE + 8 * ks + t];
        unsigned a2 = As[r0 * AS_STRIDE + 8 * ks + t + 4];
        unsigned a3 = As[(r0 + 8) * AS_STRIDE + 8 * ks + t + 4];
#pragma unroll
        for (int nt = 0; nt < 8; ++nt) {
            unsigned b0 = Wp[(8 * ks + t) * WP_STRIDE + 8 * nt + g];
            unsigned b1 = Wp[(8 * ks + t + 4) * WP_STRIDE + 8 * nt + g];
            asm("mma.sync.aligned.m16n8k16.row.col.f32.f16.f16.f32 "
                "{%0,%1,%2,%3},{%4,%5,%6,%7},{%8,%9},{%0,%1,%2,%3};"
                : "+f"(acc[nt][0]), "+f"(acc[nt][1]), "+f"(acc[nt][2]), "+f"(acc[nt][3])
                : "r"(a0), "r"(a1), "r"(a2), "r"(a3), "r"(b0), "r"(b1));
        }
    }

    int gr0 = block_row + r0;
    int gr1 = gr0 + 8;
    float ds0 = (gr0 < n) ? g_dinv[gr0] : 0.f;
    float ds1 = (gr1 < n) ? g_dinv[gr1] : 0.f;
#pragma unroll
    for (int nt = 0; nt < 8; ++nt) {
        if (gr0 < n) {
            __half2 h = __floats2half2_rn(ds0 * acc[nt][0], ds0 * acc[nt][1]);
            g_tmph[gr0 * 32 + 4 * nt + t] = h;
        }
        if (gr1 < n) {
            __half2 h = __floats2half2_rn(ds1 * acc[nt][2], ds1 * acc[nt][3]);
            g_tmph[gr1 * 32 + 4 * nt + t] = h;
        }
    }
}

// Plain GEMM launch (layers 2,3).
__global__ void k_gemm(const float* __restrict__ W, int n) {
    __shared__ unsigned As[128 * AS_STRIDE];
    __shared__ unsigned Wp[32 * WP_STRIDE];
    gemm_body(W, n, blockIdx.x, threadIdx.x, As, Wp);
}

// Fat kernel: blocks [0,nbe) scatter edges into padded CSR (fill); the rest
// run GEMM layer 1. Independent work.
__global__ void k_fill_gemm(const int* __restrict__ src, const int* __restrict__ dst,
                            int e, const float* __restrict__ W, int n, int nbe) {
    __shared__ unsigned As[128 * AS_STRIDE];
    __shared__ unsigned Wp[32 * WP_STRIDE];
    int b = blockIdx.x;
    if (b < nbe) {
        int i = b * blockDim.x + threadIdx.x;
        if (i < e) {
            int pos = atomicAdd(&g_cursor[dst[i]], 1);
            g_col[pos] = src[i];
        }
    } else {
        gemm_body(W, n, b - nbe, threadIdx.x, As, Wp);
    }
}

// ---------------------------------------------------------------------------
// Aggregation + bias + ELU. Warp per node; half2 per lane. Padded CSR.
// Unroll-16 main loop + single optional 8-group remainder. Full fp16 HADD2
// tree per 8-group (7 HADD2, 1 cvt, 2 FADD), fp32 inter-group accumulate.
// out = ELU( dinv[i]*(sum_s tmp'[s] + tmp'[i]) + b )
// ---------------------------------------------------------------------------
__device__ __forceinline__ void agg_group8(const int4 i0, const int4 i1, int lane,
                                           float& ax, float& ay) {
    __half2 v0 = g_tmph[i0.x * 32 + lane];
    __half2 v1 = g_tmph[i0.y * 32 + lane];
    __half2 v2 = g_tmph[i0.z * 32 + lane];
    __half2 v3 = g_tmph[i0.w * 32 + lane];
    __half2 v4 = g_tmph[i1.x * 32 + lane];
    __half2 v5 = g_tmph[i1.y * 32 + lane];
    __half2 v6 = g_tmph[i1.z * 32 + lane];
    __half2 v7 = g_tmph[i1.w * 32 + lane];
    __half2 s = __hadd2(__hadd2(__hadd2(v0, v1), __hadd2(v2, v3)),
                        __hadd2(__hadd2(v4, v5), __hadd2(v6, v7)));
    float2 f = __half22float2(s);
    ax += f.x;
    ay += f.y;
}

__global__ void k_agg(const float* __restrict__ bias,
                      float* __restrict__ out, int col_off, int n, int last) {
    int w = (blockIdx.x * blockDim.x + threadIdx.x) >> 5;
    int lane = threadIdx.x & 31;
    if (w >= n) return;
    int2 md = g_meta[w];                 // (rowptr, deg) — one load
    float di = g_dinv[w];
    int beg = md.x;
    int pad = (md.y + 7) & ~7;

    float ax = 0.f, ay = 0.f;
    int p = beg;
    int pend16 = beg + (pad & ~15);
    for (; p < pend16; p += 16) {
        int4 i0 = *(const int4*)&g_col[p];
        int4 i1 = *(const int4*)&g_col[p + 4];
        int4 i2 = *(const int4*)&g_col[p + 8];
        int4 i3 = *(const int4*)&g_col[p + 12];
        agg_group8(i0, i1, lane, ax, ay);
        agg_group8(i2, i3, lane, ax, ay);
    }
    if (pad & 8) {
        int4 i0 = *(const int4*)&g_col[p];
        int4 i1 = *(const int4*)&g_col[p + 4];
        agg_group8(i0, i1, lane, ax, ay);
    }
    // self-loop (tmp' already has one dinv factor) + outer dinv + bias
    float2 vs = __half22float2(g_tmph[w * 32 + lane]);
    float2 bb = ((const float2*)bias)[lane];
    ax = fmaf(di, ax + vs.x, bb.x);
    ay = fmaf(di, ay + vs.y, bb.y);
    // ELU (alpha=1)
    ax = ax > 0.f ? ax : expm1f(ax);
    ay = ay > 0.f ? ay : expm1f(ay);

    if (!last) g_hh[w * 32 + lane] = __floats2half2_rn(ax, ay);
    float* orow = out + (size_t)w * 192 + col_off;
    ((float2*)orow)[lane] = make_float2(ax, ay);
}

// ---------------------------------------------------------------------------
extern "C" void kernel_launch(void* const* d_in, const int* in_sizes, int n_in,
                              void* d_out, int out_size) {
    const float* x  = (const float*)d_in[0];
    const int*   ei = (const int*)d_in[1];
    const float* W[3] = { (const float*)d_in[2], (const float*)d_in[4], (const float*)d_in[6] };
    const float* B[3] = { (const float*)d_in[3], (const float*)d_in[5], (const float*)d_in[7] };
    int n = in_sizes[0] / 64;
    int e = in_sizes[1] / 2;
    const int* src = ei;
    const int* dst = ei + e;
    float* out = (float*)d_out;

    int nb_e = (e + 255) / 256;
    int nscan = (n + SCAN_B - 1) / SCAN_B;
    int n16 = n * 16;                        // float4 count of x
    int nb_c = (n16 + 255) / 256;            // cast blocks
    int nb_p = (MAXEP / 4 + 255) / 256;      // prefill blocks (int4)
    int gemm_blocks = (n + 127) / 128;
    int agg_blocks = (n + 7) / 8;            // 8 warps (nodes) per 256-thread block

    void* degptr = nullptr;
    cudaGetSymbolAddress(&degptr, g_deg);
    cudaMemsetAsync(degptr, 0, (size_t)n * sizeof(int));

    k_setup1<<<nb_e + nb_c + nb_p, 256>>>(dst, e, x, n16, nb_e, nb_c, n);
    k_scan<<<nscan, SCAN_B>>>(n);
    k_fill_gemm<<<nb_e + gemm_blocks, 256>>>(src, dst, e, W[0], n, nb_e);
    k_agg<<<agg_blocks, 256>>>(B[0], out, 0, n, 0);
    for (int l = 1; l < 3; ++l) {
        k_gemm<<<gemm_blocks, 256>>>(W[l], n);
        k_agg<<<agg_blocks, 256>>>(B[l], out, l * 64, n, l == 2 ? 1 : 0);
    }
}